// round 13
// baseline (speedup 1.0000x reference)
#include <cuda_runtime.h>
#include <math.h>

#define NF 3072
#define LDIM 128
#define NBATCH 8192

typedef unsigned long long ull;

// ---------------- device scratch (no allocations allowed) ----------------
__device__ float g_Mpart[16][LDIM * LDIM];  // K-split partials of W^T W
__device__ float g_M[LDIM * LDIM];          // summed M (pre-diag-add)
__device__ float g_Lp[8128];                // strict lower triangle of L, packed
__device__ float g_invdiag[LDIM];           // 1 / L[j][j]
__device__ float g_V[NF * LDIM];            // V = W L^{-T}
__device__ float g_const;
__device__ float g_inv_sigma2;

// ---------------- f32x2 helpers ----------------
__device__ __forceinline__ ull pack2(float x) {
    ull r; asm("mov.b64 %0, {%1, %1};" : "=l"(r) : "f"(x)); return r;
}
__device__ __forceinline__ void ffma2(ull& d, ull a, ull b) {
    asm("fma.rn.f32x2 %0, %1, %2, %0;" : "+l"(d) : "l"(a), "l"(b));
}
__device__ __forceinline__ void unpack2(ull v, float& lo, float& hi) {
    asm("mov.b64 {%0, %1}, %2;" : "=f"(lo), "=f"(hi) : "l"(v));
}

// ---------------- K1: partial W^T W, K-split, no atomics ----------------
// grid (2,2,16): tile 64x64 out, K-chunk 192. 256 thr = 16x16, micro 4x4.
__global__ __launch_bounds__(256, 1) void k_M(const float* __restrict__ W) {
    __shared__ __align__(16) float Wa[2][16][68];
    __shared__ __align__(16) float Wb[2][16][68];
    const int tid = threadIdx.x;
    const int ti = tid & 15, tj = tid >> 4;
    const int lf = tid >> 4, li = (tid & 15) * 4;
    const int i0 = blockIdx.x * 64, j0 = blockIdx.y * 64;
    const int kb = blockIdx.z * 192;
    float acc[4][4] = {};

    float4 a4 = *(const float4*)&W[(size_t)(kb + lf) * LDIM + i0 + li];
    float4 b4 = *(const float4*)&W[(size_t)(kb + lf) * LDIM + j0 + li];
    *(float4*)&Wa[0][lf][li] = a4;
    *(float4*)&Wb[0][lf][li] = b4;
    __syncthreads();

    for (int t = 0; t < 12; t++) {
        const int cb = t & 1, nb = cb ^ 1;
        float4 na, nbv;
        if (t < 11) {
            na  = *(const float4*)&W[(size_t)(kb + (t + 1) * 16 + lf) * LDIM + i0 + li];
            nbv = *(const float4*)&W[(size_t)(kb + (t + 1) * 16 + lf) * LDIM + j0 + li];
        }
#pragma unroll
        for (int k = 0; k < 16; k++) {
            float4 av = *(const float4*)&Wa[cb][k][ti * 4];
            float4 bv = *(const float4*)&Wb[cb][k][tj * 4];
            float aa[4] = {av.x, av.y, av.z, av.w};
            float bb[4] = {bv.x, bv.y, bv.z, bv.w};
#pragma unroll
            for (int a = 0; a < 4; a++)
#pragma unroll
                for (int b = 0; b < 4; b++) acc[a][b] += aa[a] * bb[b];
        }
        if (t < 11) {
            *(float4*)&Wa[nb][lf][li] = na;
            *(float4*)&Wb[nb][lf][li] = nbv;
        }
        __syncthreads();
    }
    float* dst = g_Mpart[blockIdx.z];
#pragma unroll
    for (int a = 0; a < 4; a++)
#pragma unroll
        for (int b = 0; b < 4; b++)
            dst[(i0 + ti * 4 + a) * LDIM + j0 + tj * 4 + b] = acc[a][b];
}

// ---------------- K2: deterministic partial sum ----------------
__global__ void k_Msum() {
    const int idx = blockIdx.x * 256 + threadIdx.x;
    float s = 0.f;
#pragma unroll
    for (int p = 0; p < 16; p++) s += g_Mpart[p][idx];
    g_M[idx] = s;
}

// ---------------- K3: single-block packed Cholesky (2 threads / row) ----------------
// Diagonal of L never written back: kept as d^2 in Ap; invdiag = rsqrt, log via 0.5*log(d^2).
// Two barriers per pivot iteration.
__global__ void k_chol(const float* __restrict__ log_var) {
    __shared__ float Ap[8256];
    __shared__ float col[LDIM];
    __shared__ float red[LDIM];
    const int tid = threadIdx.x;
    const int row = tid & 127, half = tid >> 7;
    const int off = row * (row + 1) / 2;
    const float lv = log_var[0];
    const float s2 = expf(lv);
    for (int c = half; c <= row; c += 2)
        Ap[off + c] = g_M[row * LDIM + c] + (c == row ? s2 : 0.f);
    __syncthreads();
    for (int i = 0; i < LDIM; i++) {
        const int ii = i * (i + 1) / 2;
        // Ap[ii+i] holds d^2 (never overwritten); stable since prev iter's end barrier.
        const float inv = rsqrtf(Ap[ii + i]);
        if (half == 0 && row > i) {
            float v = Ap[off + i] * inv;   // distinct address from Ap[ii+i] (row>i)
            Ap[off + i] = v;
            col[row] = v;
        }
        __syncthreads();
        if (row > i) {
            const float f = col[row];
            for (int k = i + 1 + half; k <= row; k += 2) Ap[off + k] -= f * col[k];
        }
        __syncthreads();
    }
    if (half == 0) {
        float p = Ap[off + row];           // = L[row][row]^2
        g_invdiag[row] = rsqrtf(p);
        red[row] = 0.5f * logf(p);
    }
    {
        const int soff = row * (row - 1) / 2;
        for (int c = half; c < row; c += 2) g_Lp[soff + c] = Ap[off + c];
    }
    __syncthreads();
    if (tid < 64) red[tid] += red[tid + 64];
    __syncthreads();
    if (tid < 32) {
        float s = red[tid] + red[tid + 32];
#pragma unroll
        for (int o = 16; o > 0; o >>= 1) s += __shfl_xor_sync(0xffffffffu, s, o);
        if (tid == 0) {
            float logdetM = 2.0f * s;
            g_inv_sigma2 = 1.0f / s2;
            g_const = -0.5f * ((float)(3072.0 * 1.8378770664093454)
                               + 2944.0f * lv
                               + logdetM);
        }
    }
}

// ---------------- K4: V rows by forward substitution  L v = w ----------------
// 48 blocks x 64 threads; thread t owns W-row row0+t; v lives in smem column t.
// No shuffles, no syncs in the solve loop: pure issue-bound.
__global__ __launch_bounds__(64, 1) void k_V2(const float* __restrict__ W) {
    __shared__ float vsm[LDIM][65];     // [k][thread], padded: bank = (k + t) mod 32
    const int tid = threadIdx.x;
    const int row0 = blockIdx.x * 64;

    // coalesced load of the 64x128 W tile, transposed into vsm
    for (int n = 0; n < 128; n++) {
        int i = n * 64 + tid;
        int r = i >> 7, c = i & 127;
        vsm[c][r] = W[(size_t)(row0 + r) * LDIM + c];
    }
    __syncthreads();

    // forward substitution, v overwrites w in place (each thread touches only column tid)
    for (int j = 0; j < LDIM; j++) {
        const float* Lr = g_Lp + ((j * (j - 1)) >> 1);
        float s0 = 0.f, s1 = 0.f, s2 = 0.f, s3 = 0.f;
        int k = 0;
        for (; k + 4 <= j; k += 4) {
            s0 += Lr[k]     * vsm[k][tid];
            s1 += Lr[k + 1] * vsm[k + 1][tid];
            s2 += Lr[k + 2] * vsm[k + 2][tid];
            s3 += Lr[k + 3] * vsm[k + 3][tid];
        }
        for (; k < j; k++) s0 += Lr[k] * vsm[k][tid];
        float v = (vsm[j][tid] - ((s0 + s1) + (s2 + s3))) * __ldg(&g_invdiag[j]);
        vsm[j][tid] = v;
    }

    // write out: thread t -> g_V row row0+t, vectorized 16B stores
    float* vout = g_V + (size_t)(row0 + tid) * LDIM;
    for (int k = 0; k < LDIM; k += 4) {
        float4 o = make_float4(vsm[k][tid], vsm[k + 1][tid],
                               vsm[k + 2][tid], vsm[k + 3][tid]);
        *(float4*)&vout[k] = o;
    }
}

// ---------------- K6: fused big GEMM + row norms + output ----------------
// tile 64 rows x 128 cols, KT=16, 256 thr (32x8), micro 8x4 with f32x2 row pairs.
__global__ __launch_bounds__(256, 1) void k_main(const float* __restrict__ X,
                                                 const float* __restrict__ mean,
                                                 float* __restrict__ out) {
    __shared__ __align__(16) float As[2][16][68];
    __shared__ __align__(16) float Vs[2][16][128];
    __shared__ float ssred[4][64];
    const int tid = threadIdx.x;
    const int tx = tid & 31, ty = tid >> 5;
    const int ldr = tid >> 2, lseg = tid & 3;
    const int vk = tid >> 4, vj = (tid & 15) * 8;
    const int row0 = blockIdx.x * 64;
    const float* xptr = X + (size_t)(row0 + ldr) * NF + lseg * 4;

    ull acc[4][4];
#pragma unroll
    for (int i = 0; i < 4; i++)
#pragma unroll
        for (int j = 0; j < 4; j++) acc[i][j] = 0ull;
    float ssp = 0.f;

    float4 xv = *(const float4*)(xptr);
    float4 mv = *(const float4*)(mean + lseg * 4);
    float4 va = *(const float4*)(g_V + vk * LDIM + vj);
    float4 vb = *(const float4*)(g_V + vk * LDIM + vj + 4);
    {
        float r0 = xv.x - mv.x, r1 = xv.y - mv.y, r2 = xv.z - mv.z, r3 = xv.w - mv.w;
        ssp += r0 * r0 + r1 * r1 + r2 * r2 + r3 * r3;
        As[0][lseg * 4 + 0][ldr] = r0; As[0][lseg * 4 + 1][ldr] = r1;
        As[0][lseg * 4 + 2][ldr] = r2; As[0][lseg * 4 + 3][ldr] = r3;
        *(float4*)&Vs[0][vk][vj] = va; *(float4*)&Vs[0][vk][vj + 4] = vb;
    }
    __syncthreads();

    for (int t = 0; t < NF / 16; t++) {
        const int cb = t & 1, nb = cb ^ 1;
        if (t < NF / 16 - 1) {
            const int k0 = (t + 1) * 16;
            xv = *(const float4*)(xptr + k0);
            mv = *(const float4*)(mean + k0 + lseg * 4);
            va = *(const float4*)(g_V + (size_t)(k0 + vk) * LDIM + vj);
            vb = *(const float4*)(g_V + (size_t)(k0 + vk) * LDIM + vj + 4);
        }
#pragma unroll
        for (int k = 0; k < 16; k++) {
            float4 b4 = *(const float4*)&Vs[cb][k][tx * 4];
            ull b0 = pack2(b4.x), b1 = pack2(b4.y), b2 = pack2(b4.z), b3 = pack2(b4.w);
            ulonglong2 q0 = *(const ulonglong2*)&As[cb][k][ty * 8];
            ulonglong2 q1 = *(const ulonglong2*)&As[cb][k][ty * 8 + 4];
            ull p[4] = {q0.x, q0.y, q1.x, q1.y};
#pragma unroll
            for (int rp = 0; rp < 4; rp++) {
                ffma2(acc[rp][0], p[rp], b0);
                ffma2(acc[rp][1], p[rp], b1);
                ffma2(acc[rp][2], p[rp], b2);
                ffma2(acc[rp][3], p[rp], b3);
            }
        }
        if (t < NF / 16 - 1) {
            float r0 = xv.x - mv.x, r1 = xv.y - mv.y, r2 = xv.z - mv.z, r3 = xv.w - mv.w;
            ssp += r0 * r0 + r1 * r1 + r2 * r2 + r3 * r3;
            As[nb][lseg * 4 + 0][ldr] = r0; As[nb][lseg * 4 + 1][ldr] = r1;
            As[nb][lseg * 4 + 2][ldr] = r2; As[nb][lseg * 4 + 3][ldr] = r3;
            *(float4*)&Vs[nb][vk][vj] = va; *(float4*)&Vs[nb][vk][vj + 4] = vb;
        }
        __syncthreads();
    }

    ssred[lseg][ldr] = ssp;
    __syncthreads();

    float ys[8];
#pragma unroll
    for (int i = 0; i < 8; i++) ys[i] = 0.f;
#pragma unroll
    for (int rp = 0; rp < 4; rp++)
#pragma unroll
        for (int c = 0; c < 4; c++) {
            float lo, hi;
            unpack2(acc[rp][c], lo, hi);
            ys[2 * rp]     += lo * lo;
            ys[2 * rp + 1] += hi * hi;
        }
#pragma unroll
    for (int i = 0; i < 8; i++) {
        float s = ys[i];
#pragma unroll
        for (int o = 16; o > 0; o >>= 1) s += __shfl_xor_sync(0xffffffffu, s, o);
        ys[i] = s;
    }
    if (tx == 0) {
        const float cst = g_const, is2 = g_inv_sigma2;
#pragma unroll
        for (int i = 0; i < 8; i++) {
            const int r = ty * 8 + i;
            float ss = ssred[0][r] + ssred[1][r] + ssred[2][r] + ssred[3][r];
            out[row0 + r] = cst - 0.5f * (ss - ys[i]) * is2;
        }
    }
}

// ---------------- launch ----------------
extern "C" void kernel_launch(void* const* d_in, const int* in_sizes, int n_in,
                              void* d_out, int out_size) {
    const float* X    = (const float*)d_in[0];   // [8192, 3072]
    const float* W    = (const float*)d_in[1];   // [3072, 128]
    const float* lv   = (const float*)d_in[2];   // [1]
    const float* mean = (const float*)d_in[3];   // [3072]
    float* out = (float*)d_out;                  // [8192]

    k_M<<<dim3(2, 2, 16), 256>>>(W);
    k_Msum<<<64, 256>>>();
    k_chol<<<1, 256>>>(lv);
    k_V2<<<48, 64>>>(W);
    k_main<<<128, 256>>>(X, mean, out);
}